// round 5
// baseline (speedup 1.0000x reference)
#include <cuda_runtime.h>
#include <math.h>

#define BSZ 2
#define TSZ 2048
#define DMODEL 2048
#define QHEADS 16
#define KVHEADS 4
#define HDIM 128
#define NTOK (BSZ*TSZ)          // 4096
#define QO (QHEADS*HDIM)        // 2048
#define KO (KVHEADS*HDIM)       // 512

// Scratch (device globals: allocation-rule-safe)
__device__ float g_Q[(size_t)NTOK*QO];
__device__ float g_K[(size_t)NTOK*KO];
__device__ float g_V[(size_t)NTOK*KO];
__device__ float g_ctx[(size_t)NTOK*QO];
__device__ float g_logits[(size_t)BSZ*QHEADS*(size_t)TSZ*TSZ];

// ---------------------------------------------------------------------------
// Naive projection: Y[n, o] = sum_d A[n*KD + d] * W[o*KD + d]
// One thread per output element; serial dot product.
// ---------------------------------------------------------------------------
__global__ void naive_proj(const float* __restrict__ A,
                           const float* __restrict__ W,
                           float* __restrict__ Y,
                           int OUTD, int KD) {
    long long idx = (long long)blockIdx.x * blockDim.x + threadIdx.x;
    long long total = (long long)NTOK * OUTD;
    if (idx >= total) return;
    int n = (int)(idx / OUTD);
    int o = (int)(idx % OUTD);
    const float* ar = A + (size_t)n * KD;
    const float* wr = W + (size_t)o * KD;
    float s = 0.0f;
    for (int d = 0; d < KD; d++) s += ar[d] * wr[d];
    Y[idx] = s;
}

// ---------------------------------------------------------------------------
// Naive RoPE, literal transcription of _apply_rotary:
//   half = 64; inv_freq[i] = 1 / 10000^(i/64); ang = pos * inv_freq
//   out[:64] = x1*cos - x2*sin ; out[64:] = x1*sin + x2*cos
// buf layout [n, h, d]; positions literal int32 buffer, index n.
// ---------------------------------------------------------------------------
__global__ void naive_rope(float* __restrict__ buf,
                           const int* __restrict__ positions,
                           int nheads) {
    long long idx = (long long)blockIdx.x * blockDim.x + threadIdx.x;
    long long total = (long long)NTOK * nheads * 64;
    if (idx >= total) return;
    int i = (int)(idx % 64);
    int h = (int)((idx / 64) % nheads);
    int n = (int)(idx / (64 * nheads));
    float pos = (float)positions[n];
    float inv = powf(10000.0f, -(float)i / 64.0f);
    float ang = pos * inv;
    float c = cosf(ang);
    float s = sinf(ang);
    size_t base = ((size_t)n * nheads + h) * HDIM;
    float x1 = buf[base + i];
    float x2 = buf[base + 64 + i];
    buf[base + i]      = x1 * c - x2 * s;
    buf[base + 64 + i] = x1 * s + x2 * c;
}

// ---------------------------------------------------------------------------
// Naive logits: L[b,h,t,T] = (q[b,t,h,:] . k[b,T,h/4,:]) / sqrt(128),
// then where(T<=t, ., -1e9). One thread per logit.
// ---------------------------------------------------------------------------
__global__ void naive_logits(const float* __restrict__ Q,
                             const float* __restrict__ K,
                             float* __restrict__ L) {
    long long idx = (long long)blockIdx.x * blockDim.x + threadIdx.x;
    long long total = (long long)BSZ * QHEADS * TSZ * TSZ;
    if (idx >= total) return;
    int T  = (int)(idx % TSZ);
    long long r = idx / TSZ;
    int t  = (int)(r % TSZ);
    int bh = (int)(r / TSZ);
    int b = bh / QHEADS;
    int h = bh % QHEADS;
    const float* qr = Q + ((size_t)(b * TSZ + t) * QHEADS + h) * HDIM;
    const float* kr = K + ((size_t)(b * TSZ + T) * KVHEADS + (h / 4)) * HDIM;
    float s = 0.0f;
    for (int d = 0; d < HDIM; d++) s += qr[d] * kr[d];
    s *= 0.08838834764831845f;             // 1/sqrt(128)
    if (T > t) s = -1000000000.0f;         // reference mask value
    L[idx] = s;
}

// ---------------------------------------------------------------------------
// Naive softmax over the full row (masked entries underflow to exactly 0,
// matching jax.nn.softmax on -1e9-masked logits). One thread per row.
// ---------------------------------------------------------------------------
__global__ void naive_softmax(float* __restrict__ L) {
    int row = blockIdx.x * blockDim.x + threadIdx.x;
    if (row >= BSZ * QHEADS * TSZ) return;
    float* p = L + (size_t)row * TSZ;
    float mx = -INFINITY;
    for (int j = 0; j < TSZ; j++) mx = fmaxf(mx, p[j]);
    float sum = 0.0f;
    for (int j = 0; j < TSZ; j++) {
        float e = expf(p[j] - mx);
        p[j] = e;
        sum += e;
    }
    float inv = 1.0f / sum;
    for (int j = 0; j < TSZ; j++) p[j] *= inv;
}

// ---------------------------------------------------------------------------
// Naive PV: ctx[b,t,h,d] = sum_T P[b,h,t,T] * v[b,T,h/4,d].
// One thread per ctx element. Output layout [n, h*128+d] (= bto reshape).
// ---------------------------------------------------------------------------
__global__ void naive_pv(const float* __restrict__ L,
                         const float* __restrict__ V,
                         float* __restrict__ ctx) {
    long long idx = (long long)blockIdx.x * blockDim.x + threadIdx.x;
    long long total = (long long)NTOK * QHEADS * HDIM;
    if (idx >= total) return;
    int d = (int)(idx % HDIM);
    long long r = idx / HDIM;
    int h = (int)(r % QHEADS);
    long long nt = r / QHEADS;
    int t = (int)(nt % TSZ);
    int b = (int)(nt / TSZ);
    const float* pr = L + ((size_t)(b * QHEADS + h) * TSZ + t) * TSZ;
    const float* vb = V + ((size_t)(b * TSZ) * KVHEADS + (h / 4)) * HDIM + d;
    float s = 0.0f;
    for (int T = 0; T < TSZ; T++)
        s += pr[T] * vb[(size_t)T * KO];
    ctx[((size_t)(b * TSZ + t) * QHEADS + h) * HDIM + d] = s;
}

// ---------------------------------------------------------------------------
extern "C" void kernel_launch(void* const* d_in, const int* in_sizes, int n_in,
                              void* d_out, int out_size) {
    (void)in_sizes; (void)n_in; (void)out_size;

    // Literal setup_inputs order: x, positions, wq, wk, wv, wo
    const float* x   = (const float*)d_in[0];
    const int*   pos = (const int*)  d_in[1];
    const float* wq  = (const float*)d_in[2];
    const float* wk  = (const float*)d_in[3];
    const float* wv  = (const float*)d_in[4];
    const float* wo  = (const float*)d_in[5];
    float* out = (float*)d_out;

    float *Qp, *Kp, *Vp, *Cp, *Lp;
    cudaGetSymbolAddress((void**)&Qp, g_Q);
    cudaGetSymbolAddress((void**)&Kp, g_K);
    cudaGetSymbolAddress((void**)&Vp, g_V);
    cudaGetSymbolAddress((void**)&Cp, g_ctx);
    cudaGetSymbolAddress((void**)&Lp, g_logits);

    const int TPB = 256;
    auto blocks = [](long long n, int tpb) { return (unsigned)((n + tpb - 1) / tpb); };

    // q = x @ wq^T ; k = x @ wk^T ; v = x @ wv^T
    naive_proj<<<blocks((long long)NTOK*QO, TPB), TPB>>>(x, wq, Qp, QO, DMODEL);
    naive_proj<<<blocks((long long)NTOK*KO, TPB), TPB>>>(x, wk, Kp, KO, DMODEL);
    naive_proj<<<blocks((long long)NTOK*KO, TPB), TPB>>>(x, wv, Vp, KO, DMODEL);

    // RoPE on q and k
    naive_rope<<<blocks((long long)NTOK*QHEADS*64, TPB), TPB>>>(Qp, pos, QHEADS);
    naive_rope<<<blocks((long long)NTOK*KVHEADS*64, TPB), TPB>>>(Kp, pos, KVHEADS);

    // logits -> softmax -> ctx
    naive_logits<<<blocks((long long)BSZ*QHEADS*TSZ*TSZ, TPB), TPB>>>(Qp, Kp, Lp);
    naive_softmax<<<blocks((long long)BSZ*QHEADS*TSZ, TPB), TPB>>>(Lp);
    naive_pv<<<blocks((long long)NTOK*QHEADS*HDIM, TPB), TPB>>>(Lp, Vp, Cp);

    // out = ctx @ wo^T
    naive_proj<<<blocks((long long)NTOK*DMODEL, TPB), TPB>>>(Cp, wo, out, DMODEL, QO);
}

// round 6
// speedup vs baseline: 59.2251x; 59.2251x over previous
#include <cuda_runtime.h>
#include <math.h>

#define BSZ 2
#define TSZ 2048
#define DMODEL 2048
#define QHEADS 16
#define KVHEADS 4
#define HDIM 128
#define NTOK (BSZ*TSZ)          // 4096
#define QO (QHEADS*HDIM)        // 2048
#define KO (KVHEADS*HDIM)       // 512

// Scratch (device globals: allocation-rule-safe)
__device__ float g_Q[(size_t)NTOK*QO];
__device__ float g_K[(size_t)NTOK*KO];
__device__ float g_V[(size_t)NTOK*KO];
__device__ float g_ctx[(size_t)NTOK*QO];
__device__ float g_logits[(size_t)BSZ*QHEADS*(size_t)TSZ*TSZ];

// ---------------------------------------------------------------------------
// GEMM: C[M,N] = A[M,K] * B[N,K]^T. Fresh implementation: 128x64 block tile,
// BK=16, 256 threads, 8x4 microtile, k-major (transposed) smem, float4 I/O.
// Requires M%128==0, N%64==0, K%16==0 (all shapes here satisfy this).
// ---------------------------------------------------------------------------
__global__ void gemm_tile(const float* __restrict__ A,
                          const float* __restrict__ B,
                          float* __restrict__ C,
                          int N, int K) {
    __shared__ float As[16][132];   // [k][m], padded
    __shared__ float Bs[16][68];    // [k][n], padded
    const int t = threadIdx.x;
    const int bm = blockIdx.y * 128, bn = blockIdx.x * 64;
    const int tm = (t >> 4) * 8;    // 8 M-rows per thread
    const int tn = (t & 15) * 4;    // 4 N-cols per thread

    float acc[8][4];
    #pragma unroll
    for (int i = 0; i < 8; i++)
        #pragma unroll
        for (int j = 0; j < 4; j++) acc[i][j] = 0.0f;

    for (int k0 = 0; k0 < K; k0 += 16) {
        // Load A tile: 128 rows x 16 cols = 512 float4, 2 per thread
        #pragma unroll
        for (int e = 0; e < 2; e++) {
            int f = t + e * 256;
            int r = f >> 2, c4 = (f & 3) * 4;
            float4 a4 = *(const float4*)(A + (size_t)(bm + r) * K + k0 + c4);
            As[c4+0][r] = a4.x; As[c4+1][r] = a4.y;
            As[c4+2][r] = a4.z; As[c4+3][r] = a4.w;
        }
        // Load B tile: 64 rows x 16 cols = 256 float4, 1 per thread
        {
            int r = t >> 2, c4 = (t & 3) * 4;
            float4 b4 = *(const float4*)(B + (size_t)(bn + r) * K + k0 + c4);
            Bs[c4+0][r] = b4.x; Bs[c4+1][r] = b4.y;
            Bs[c4+2][r] = b4.z; Bs[c4+3][r] = b4.w;
        }
        __syncthreads();

        #pragma unroll
        for (int kk = 0; kk < 16; kk++) {
            float4 a0 = *(const float4*)&As[kk][tm];
            float4 a1 = *(const float4*)&As[kk][tm + 4];
            float4 bv = *(const float4*)&Bs[kk][tn];
            float am[8] = {a0.x, a0.y, a0.z, a0.w, a1.x, a1.y, a1.z, a1.w};
            float bb[4] = {bv.x, bv.y, bv.z, bv.w};
            #pragma unroll
            for (int i = 0; i < 8; i++)
                #pragma unroll
                for (int j = 0; j < 4; j++)
                    acc[i][j] += am[i] * bb[j];
        }
        __syncthreads();
    }

    #pragma unroll
    for (int i = 0; i < 8; i++) {
        float4 o = make_float4(acc[i][0], acc[i][1], acc[i][2], acc[i][3]);
        *(float4*)(C + (size_t)(bm + tm + i) * N + bn + tn) = o;
    }
}

// ---------------------------------------------------------------------------
// RoPE — unchanged from the proven round-5 kernel (literal transcription).
// ---------------------------------------------------------------------------
__global__ void naive_rope(float* __restrict__ buf,
                           const int* __restrict__ positions,
                           int nheads) {
    long long idx = (long long)blockIdx.x * blockDim.x + threadIdx.x;
    long long total = (long long)NTOK * nheads * 64;
    if (idx >= total) return;
    int i = (int)(idx % 64);
    int h = (int)((idx / 64) % nheads);
    int n = (int)(idx / (64 * nheads));
    float pos = (float)positions[n];
    float inv = powf(10000.0f, -(float)i / 64.0f);
    float ang = pos * inv;
    float c = cosf(ang);
    float s = sinf(ang);
    size_t base = ((size_t)n * nheads + h) * HDIM;
    float x1 = buf[base + i];
    float x2 = buf[base + 64 + i];
    buf[base + i]      = x1 * c - x2 * s;
    buf[base + 64 + i] = x1 * s + x2 * c;
}

// ---------------------------------------------------------------------------
// Logits, tiled: 64x64 tile per block. Every entry of L gets written
// (above-diagonal blocks fill -1e9), so downstream softmax is a plain full
// row softmax — identical semantics to the proven naive pipeline.
// d-major smem staging, float4 LDS in the dot loop.
// ---------------------------------------------------------------------------
__global__ void logits_t(const float* __restrict__ Q,
                         const float* __restrict__ Kg,
                         float* __restrict__ L) {
    extern __shared__ float sh[];
    float* Qs = sh;                 // [128][68] d-major
    float* Ks = sh + 128 * 68;      // [128][68]

    const int kt = blockIdx.x, qt = blockIdx.y, bh = blockIdx.z;
    const int t = threadIdx.x;
    const size_t Lbase = (size_t)bh * TSZ * TSZ;

    if (kt > qt) {                  // fully-masked tile: fill -1e9
        for (int e = t; e < 64 * 64; e += 256) {
            int r = e >> 6, c = e & 63;
            L[Lbase + (size_t)(qt * 64 + r) * TSZ + kt * 64 + c] = -1000000000.0f;
        }
        return;
    }

    const int b = bh >> 4, h = bh & 15;
    const int kvh = h >> 2;

    for (int e = t; e < 64 * 128; e += 256) {
        int r = e >> 7, d = e & 127;
        Qs[d * 68 + r] = Q[(size_t)(b * TSZ + qt * 64 + r) * QO + h * HDIM + d];
        Ks[d * 68 + r] = Kg[(size_t)(b * TSZ + kt * 64 + r) * KO + kvh * HDIM + d];
    }
    __syncthreads();

    const int tm = (t >> 4) * 4, tn = (t & 15) * 4;
    float acc[4][4];
    #pragma unroll
    for (int i = 0; i < 4; i++)
        #pragma unroll
        for (int j = 0; j < 4; j++) acc[i][j] = 0.0f;

    #pragma unroll 4
    for (int d = 0; d < 128; d++) {
        float4 a = *(const float4*)&Qs[d * 68 + tm];
        float4 bv = *(const float4*)&Ks[d * 68 + tn];
        float am[4] = {a.x, a.y, a.z, a.w};
        float bb[4] = {bv.x, bv.y, bv.z, bv.w};
        #pragma unroll
        for (int i = 0; i < 4; i++)
            #pragma unroll
            for (int j = 0; j < 4; j++)
                acc[i][j] += am[i] * bb[j];
    }

    const float sc = 0.08838834764831845f;   // 1/sqrt(128)
    #pragma unroll
    for (int i = 0; i < 4; i++) {
        int qrow = qt * 64 + tm + i;
        float v[4];
        #pragma unroll
        for (int j = 0; j < 4; j++) {
            int kcol = kt * 64 + tn + j;
            v[j] = acc[i][j] * sc;
            if (kcol > qrow) v[j] = -1000000000.0f;
        }
        float4 o = make_float4(v[0], v[1], v[2], v[3]);
        *(float4*)(L + Lbase + (size_t)qrow * TSZ + kt * 64 + tn) = o;
    }
}

// ---------------------------------------------------------------------------
// Softmax: one block per row, row staged through smem (8 KB), full 2048
// entries (all defined; masked ones underflow to exactly 0 like jax).
// ---------------------------------------------------------------------------
__global__ void softmax_t(float* __restrict__ L) {
    extern __shared__ float sh[];
    float* srow = sh;               // [2048]
    __shared__ float red[256];
    const int t = threadIdx.x;
    float* p = L + (size_t)blockIdx.x * TSZ;

    float mx = -1e30f;
    for (int j = t; j < TSZ; j += 256) {
        float v = p[j];
        srow[j] = v;
        mx = fmaxf(mx, v);
    }
    red[t] = mx;
    __syncthreads();
    for (int s = 128; s > 0; s >>= 1) {
        if (t < s) red[t] = fmaxf(red[t], red[t + s]);
        __syncthreads();
    }
    mx = red[0];
    __syncthreads();

    float sum = 0.0f;
    for (int j = t; j < TSZ; j += 256) {
        float e = expf(srow[j] - mx);
        srow[j] = e;
        sum += e;
    }
    red[t] = sum;
    __syncthreads();
    for (int s = 128; s > 0; s >>= 1) {
        if (t < s) red[t] += red[t + s];
        __syncthreads();
    }
    float inv = 1.0f / red[0];
    __syncthreads();

    for (int j = t; j < TSZ; j += 256) p[j] = srow[j] * inv;
}

// ---------------------------------------------------------------------------
// PV: ctx[b,t,h,d] = sum_T P[b,h,t,T] * V[b,T,h/4,d]. 64 rows x 128 d per
// block, key tiles kt <= qt only (P is exactly 0 beyond t). 8x4 microtile,
// kk unrolled by 4 with float4 P reads.
// ---------------------------------------------------------------------------
__global__ void pv_t(const float* __restrict__ L,
                     const float* __restrict__ V,
                     float* __restrict__ ctx) {
    extern __shared__ float sh[];
    float* Ps = sh;                 // [64][68]
    float* Vs = sh + 64 * 68;       // [64][128]

    const int qt = blockIdx.x, h = blockIdx.y, b = blockIdx.z;
    const int kvh = h >> 2;
    const int bh = b * QHEADS + h;
    const int t = threadIdx.x;
    const int tx = t & 31;          // d-group: 4 consecutive d = tx*4
    const int ty = t >> 5;          // row-group: 8 rows = ty*8..+7

    float acc[8][4];
    #pragma unroll
    for (int i = 0; i < 8; i++)
        #pragma unroll
        for (int j = 0; j < 4; j++) acc[i][j] = 0.0f;

    for (int kt = 0; kt <= qt; kt++) {
        for (int e = t; e < 64 * 128; e += 256) {
            int r = e >> 7, d = e & 127;
            Vs[r * 128 + d] =
                V[(size_t)(b * TSZ + kt * 64 + r) * KO + kvh * HDIM + d];
        }
        for (int e = t; e < 64 * 64; e += 256) {
            int r = e >> 6, c = e & 63;
            Ps[r * 68 + c] = L[(size_t)bh * TSZ * TSZ
                               + (size_t)(qt * 64 + r) * TSZ + kt * 64 + c];
        }
        __syncthreads();

        #pragma unroll 2
        for (int kk = 0; kk < 64; kk += 4) {
            float4 v0 = *(const float4*)&Vs[(kk + 0) * 128 + tx * 4];
            float4 v1 = *(const float4*)&Vs[(kk + 1) * 128 + tx * 4];
            float4 v2 = *(const float4*)&Vs[(kk + 2) * 128 + tx * 4];
            float4 v3 = *(const float4*)&Vs[(kk + 3) * 128 + tx * 4];
            #pragma unroll
            for (int i = 0; i < 8; i++) {
                float4 pq = *(const float4*)&Ps[(ty * 8 + i) * 68 + kk];
                acc[i][0] += pq.x * v0.x + pq.y * v1.x + pq.z * v2.x + pq.w * v3.x;
                acc[i][1] += pq.x * v0.y + pq.y * v1.y + pq.z * v2.y + pq.w * v3.y;
                acc[i][2] += pq.x * v0.z + pq.y * v1.z + pq.z * v2.z + pq.w * v3.z;
                acc[i][3] += pq.x * v0.w + pq.y * v1.w + pq.z * v2.w + pq.w * v3.w;
            }
        }
        __syncthreads();
    }

    #pragma unroll
    for (int i = 0; i < 8; i++) {
        float4 o = make_float4(acc[i][0], acc[i][1], acc[i][2], acc[i][3]);
        *(float4*)(ctx + (size_t)(b * TSZ + qt * 64 + ty * 8 + i) * QO
                   + h * HDIM + tx * 4) = o;
    }
}

// ---------------------------------------------------------------------------
extern "C" void kernel_launch(void* const* d_in, const int* in_sizes, int n_in,
                              void* d_out, int out_size) {
    (void)in_sizes; (void)n_in; (void)out_size;

    // Literal setup_inputs order (proven in round 5): x, positions, wq, wk, wv, wo
    const float* x   = (const float*)d_in[0];
    const int*   pos = (const int*)  d_in[1];
    const float* wq  = (const float*)d_in[2];
    const float* wk  = (const float*)d_in[3];
    const float* wv  = (const float*)d_in[4];
    const float* wo  = (const float*)d_in[5];
    float* out = (float*)d_out;

    float *Qp, *Kp, *Vp, *Cp, *Lp;
    cudaGetSymbolAddress((void**)&Qp, g_Q);
    cudaGetSymbolAddress((void**)&Kp, g_K);
    cudaGetSymbolAddress((void**)&Vp, g_V);
    cudaGetSymbolAddress((void**)&Cp, g_ctx);
    cudaGetSymbolAddress((void**)&Lp, g_logits);

    const int TPB = 256;

    // Projections: Y = X * W^T
    gemm_tile<<<dim3(QO/64, NTOK/128), TPB>>>(x, wq, Qp, QO, DMODEL);
    gemm_tile<<<dim3(KO/64, NTOK/128), TPB>>>(x, wk, Kp, KO, DMODEL);
    gemm_tile<<<dim3(KO/64, NTOK/128), TPB>>>(x, wv, Vp, KO, DMODEL);

    // RoPE (proven naive kernel)
    naive_rope<<<(unsigned)(((long long)NTOK*QHEADS*64 + TPB-1)/TPB), TPB>>>(Qp, pos, QHEADS);
    naive_rope<<<(unsigned)(((long long)NTOK*KVHEADS*64 + TPB-1)/TPB), TPB>>>(Kp, pos, KVHEADS);

    // Attention: logits -> softmax -> P@V
    int lg_sh = 2 * 128 * 68 * (int)sizeof(float);   // 69632
    cudaFuncSetAttribute(logits_t, cudaFuncAttributeMaxDynamicSharedMemorySize, lg_sh);
    logits_t<<<dim3(TSZ/64, TSZ/64, BSZ*QHEADS), TPB, lg_sh>>>(Qp, Kp, Lp);

    int sm_sh = TSZ * (int)sizeof(float);            // 8192
    softmax_t<<<BSZ*QHEADS*TSZ, TPB, sm_sh>>>(Lp);

    int pv_sh = (64*68 + 64*128) * (int)sizeof(float);  // 50176
    cudaFuncSetAttribute(pv_t, cudaFuncAttributeMaxDynamicSharedMemorySize, pv_sh);
    pv_t<<<dim3(TSZ/64, QHEADS, BSZ), TPB, pv_sh>>>(Lp, Vp, Cp);

    // Output projection
    gemm_tile<<<dim3(DMODEL/64, NTOK/128), TPB>>>(Cp, wo, out, DMODEL, QO);
}

// round 8
// speedup vs baseline: 67.3576x; 1.1373x over previous
#include <cuda_runtime.h>
#include <cuda_bf16.h>
#include <math.h>
#include <cstdint>

#define BSZ 2
#define TSZ 2048
#define DMODEL 2048
#define QHEADS 16
#define KVHEADS 4
#define HDIM 128
#define NTOK (BSZ*TSZ)          // 4096
#define QO (QHEADS*HDIM)        // 2048
#define KO (KVHEADS*HDIM)       // 512

// Scratch (device globals: allocation-rule-safe)
__device__ float g_Q[(size_t)NTOK*QO];
__device__ float g_K[(size_t)NTOK*KO];
__device__ float g_V[(size_t)NTOK*KO];
__device__ float g_ctx[(size_t)NTOK*QO];
__device__ float g_logits[(size_t)BSZ*QHEADS*(size_t)TSZ*TSZ];

// ---------------------------------------------------------------------------
// bf16x3 tensor-core GEMM: C[M,N] = A[M,K] * B[N,K]^T  (fp32 in/out).
// Each fp32 operand is split x = hi + lo (both bf16); the product is
// reconstructed as Ahi*Bhi + Ahi*Blo + Alo*Bhi (error ~2^-17).
// Block tile 128x64, BK=16, 8 warps (256 thr), warp tile 32x32,
// mma.sync.m16n8k16 bf16 with fp32 accumulate.
// Requires M%128==0, N%64==0, K%16==0.
// ---------------------------------------------------------------------------
#define MMA_BF16(d, a0,a1,a2,a3, b0,b1)                                       \
    asm volatile(                                                             \
        "mma.sync.aligned.m16n8k16.row.col.f32.bf16.bf16.f32 "                \
        "{%0,%1,%2,%3},{%4,%5,%6,%7},{%8,%9},{%0,%1,%2,%3};"                  \
        : "+f"(d[0]), "+f"(d[1]), "+f"(d[2]), "+f"(d[3])                      \
        : "r"(a0), "r"(a1), "r"(a2), "r"(a3), "r"(b0), "r"(b1))

__device__ __forceinline__ void split_bf16(float x, __nv_bfloat16& h,
                                           __nv_bfloat16& l) {
    h = __float2bfloat16(x);
    l = __float2bfloat16(x - __bfloat162float(h));
}

__global__ void gemm_bf16x3(const float* __restrict__ A,
                            const float* __restrict__ B,
                            float* __restrict__ C,
                            int N, int K) {
    __shared__ __nv_bfloat16 Ah[128][18], Al[128][18];
    __shared__ __nv_bfloat16 Bh[64][18],  Bl[64][18];

    const int t    = threadIdx.x;
    const int lane = t & 31;
    const int wid  = t >> 5;
    const int wm   = wid >> 1;      // 0..3  (M direction, 32 rows each)
    const int wn   = wid & 1;       // 0..1  (N direction, 32 cols each)
    const int bm   = blockIdx.y * 128, bn = blockIdx.x * 64;
    const int lr   = lane >> 2;           // 0..7
    const int lc   = (lane & 3) * 2;      // 0,2,4,6

    float acc[2][4][4];
    #pragma unroll
    for (int mf = 0; mf < 2; mf++)
        #pragma unroll
        for (int nf = 0; nf < 4; nf++)
            #pragma unroll
            for (int e = 0; e < 4; e++) acc[mf][nf][e] = 0.0f;

    for (int k0 = 0; k0 < K; k0 += 16) {
        // Stage A tile (128x16): 512 float4, 2 per thread, split hi/lo
        #pragma unroll
        for (int e = 0; e < 2; e++) {
            int f = t + e * 256;
            int r = f >> 2, c = (f & 3) * 4;
            float4 v = *(const float4*)(A + (size_t)(bm + r) * K + k0 + c);
            split_bf16(v.x, Ah[r][c+0], Al[r][c+0]);
            split_bf16(v.y, Ah[r][c+1], Al[r][c+1]);
            split_bf16(v.z, Ah[r][c+2], Al[r][c+2]);
            split_bf16(v.w, Ah[r][c+3], Al[r][c+3]);
        }
        // Stage B tile (64x16): 256 float4, 1 per thread
        {
            int r = t >> 2, c = (t & 3) * 4;
            float4 v = *(const float4*)(B + (size_t)(bn + r) * K + k0 + c);
            split_bf16(v.x, Bh[r][c+0], Bl[r][c+0]);
            split_bf16(v.y, Bh[r][c+1], Bl[r][c+1]);
            split_bf16(v.z, Bh[r][c+2], Bl[r][c+2]);
            split_bf16(v.w, Bh[r][c+3], Bl[r][c+3]);
        }
        __syncthreads();

        // B fragments (k16n8, col-major = [n][k]): 4 n-frags x {hi,lo}
        uint32_t bh[4][2], bl[4][2];
        #pragma unroll
        for (int nf = 0; nf < 4; nf++) {
            int n0 = wn * 32 + nf * 8 + lr;
            bh[nf][0] = *(const uint32_t*)&Bh[n0][lc];
            bh[nf][1] = *(const uint32_t*)&Bh[n0][lc + 8];
            bl[nf][0] = *(const uint32_t*)&Bl[n0][lc];
            bl[nf][1] = *(const uint32_t*)&Bl[n0][lc + 8];
        }

        #pragma unroll
        for (int mf = 0; mf < 2; mf++) {
            int m0 = wm * 32 + mf * 16 + lr;
            uint32_t ah0 = *(const uint32_t*)&Ah[m0][lc];
            uint32_t ah1 = *(const uint32_t*)&Ah[m0 + 8][lc];
            uint32_t ah2 = *(const uint32_t*)&Ah[m0][lc + 8];
            uint32_t ah3 = *(const uint32_t*)&Ah[m0 + 8][lc + 8];
            uint32_t al0 = *(const uint32_t*)&Al[m0][lc];
            uint32_t al1 = *(const uint32_t*)&Al[m0 + 8][lc];
            uint32_t al2 = *(const uint32_t*)&Al[m0][lc + 8];
            uint32_t al3 = *(const uint32_t*)&Al[m0 + 8][lc + 8];
            #pragma unroll
            for (int nf = 0; nf < 4; nf++) {
                MMA_BF16(acc[mf][nf], ah0, ah1, ah2, ah3, bh[nf][0], bh[nf][1]);
                MMA_BF16(acc[mf][nf], ah0, ah1, ah2, ah3, bl[nf][0], bl[nf][1]);
                MMA_BF16(acc[mf][nf], al0, al1, al2, al3, bh[nf][0], bh[nf][1]);
            }
        }
        __syncthreads();
    }

    // Epilogue: c0,c1 = (row, col..col+1); c2,c3 = (row+8, col..col+1)
    #pragma unroll
    for (int mf = 0; mf < 2; mf++) {
        #pragma unroll
        for (int nf = 0; nf < 4; nf++) {
            int r0 = bm + wm * 32 + mf * 16 + lr;
            int c0 = bn + wn * 32 + nf * 8 + lc;
            float2 v0 = make_float2(acc[mf][nf][0], acc[mf][nf][1]);
            float2 v1 = make_float2(acc[mf][nf][2], acc[mf][nf][3]);
            *(float2*)(C + (size_t)r0 * N + c0)       = v0;
            *(float2*)(C + (size_t)(r0 + 8) * N + c0) = v1;
        }
    }
}

// ---------------------------------------------------------------------------
// RoPE — proven round-5/6 kernel, unchanged.
// ---------------------------------------------------------------------------
__global__ void naive_rope(float* __restrict__ buf,
                           const int* __restrict__ positions,
                           int nheads) {
    long long idx = (long long)blockIdx.x * blockDim.x + threadIdx.x;
    long long total = (long long)NTOK * nheads * 64;
    if (idx >= total) return;
    int i = (int)(idx % 64);
    int h = (int)((idx / 64) % nheads);
    int n = (int)(idx / (64 * nheads));
    float pos = (float)positions[n];
    float inv = powf(10000.0f, -(float)i / 64.0f);
    float ang = pos * inv;
    float c = cosf(ang);
    float s = sinf(ang);
    size_t base = ((size_t)n * nheads + h) * HDIM;
    float x1 = buf[base + i];
    float x2 = buf[base + 64 + i];
    buf[base + i]      = x1 * c - x2 * s;
    buf[base + 64 + i] = x1 * s + x2 * c;
}

// ---------------------------------------------------------------------------
// Logits — proven round-6 kernel, unchanged.
// ---------------------------------------------------------------------------
__global__ void logits_t(const float* __restrict__ Q,
                         const float* __restrict__ Kg,
                         float* __restrict__ L) {
    extern __shared__ float sh[];
    float* Qs = sh;                 // [128][68] d-major
    float* Ks = sh + 128 * 68;      // [128][68]

    const int kt = blockIdx.x, qt = blockIdx.y, bh = blockIdx.z;
    const int t = threadIdx.x;
    const size_t Lbase = (size_t)bh * TSZ * TSZ;

    if (kt > qt) {                  // fully-masked tile: fill -1e9
        for (int e = t; e < 64 * 64; e += 256) {
            int r = e >> 6, c = e & 63;
            L[Lbase + (size_t)(qt * 64 + r) * TSZ + kt * 64 + c] = -1000000000.0f;
        }
        return;
    }

    const int b = bh >> 4, h = bh & 15;
    const int kvh = h >> 2;

    for (int e = t; e < 64 * 128; e += 256) {
        int r = e >> 7, d = e & 127;
        Qs[d * 68 + r] = Q[(size_t)(b * TSZ + qt * 64 + r) * QO + h * HDIM + d];
        Ks[d * 68 + r] = Kg[(size_t)(b * TSZ + kt * 64 + r) * KO + kvh * HDIM + d];
    }
    __syncthreads();

    const int tm = (t >> 4) * 4, tn = (t & 15) * 4;
    float acc[4][4];
    #pragma unroll
    for (int i = 0; i < 4; i++)
        #pragma unroll
        for (int j = 0; j < 4; j++) acc[i][j] = 0.0f;

    #pragma unroll 4
    for (int d = 0; d < 128; d++) {
        float4 a = *(const float4*)&Qs[d * 68 + tm];
        float4 bv = *(const float4*)&Ks[d * 68 + tn];
        float am[4] = {a.x, a.y, a.z, a.w};
        float bb[4] = {bv.x, bv.y, bv.z, bv.w};
        #pragma unroll
        for (int i = 0; i < 4; i++)
            #pragma unroll
            for (int j = 0; j < 4; j++)
                acc[i][j] += am[i] * bb[j];
    }

    const float sc = 0.08838834764831845f;   // 1/sqrt(128)
    #pragma unroll
    for (int i = 0; i < 4; i++) {
        int qrow = qt * 64 + tm + i;
        float v[4];
        #pragma unroll
        for (int j = 0; j < 4; j++) {
            int kcol = kt * 64 + tn + j;
            v[j] = acc[i][j] * sc;
            if (kcol > qrow) v[j] = -1000000000.0f;
        }
        float4 o = make_float4(v[0], v[1], v[2], v[3]);
        *(float4*)(L + Lbase + (size_t)qrow * TSZ + kt * 64 + tn) = o;
    }
}

// ---------------------------------------------------------------------------
// Softmax — proven round-6 kernel, unchanged.
// ---------------------------------------------------------------------------
__global__ void softmax_t(float* __restrict__ L) {
    extern __shared__ float sh[];
    float* srow = sh;               // [2048]
    __shared__ float red[256];
    const int t = threadIdx.x;
    float* p = L + (size_t)blockIdx.x * TSZ;

    float mx = -1e30f;
    for (int j = t; j < TSZ; j += 256) {
        float v = p[j];
        srow[j] = v;
        mx = fmaxf(mx, v);
    }
    red[t] = mx;
    __syncthreads();
    for (int s = 128; s > 0; s >>= 1) {
        if (t < s) red[t] = fmaxf(red[t], red[t + s]);
        __syncthreads();
    }
    mx = red[0];
    __syncthreads();

    float sum = 0.0f;
    for (int j = t; j < TSZ; j += 256) {
        float e = expf(srow[j] - mx);
        srow[j] = e;
        sum += e;
    }
    red[t] = sum;
    __syncthreads();
    for (int s = 128; s > 0; s >>= 1) {
        if (t < s) red[t] += red[t + s];
        __syncthreads();
    }
    float inv = 1.0f / red[0];
    __syncthreads();

    for (int j = t; j < TSZ; j += 256) p[j] = srow[j] * inv;
}

// ---------------------------------------------------------------------------
// PV — proven round-6 kernel, unchanged.
// ---------------------------------------------------------------------------
__global__ void pv_t(const float* __restrict__ L,
                     const float* __restrict__ V,
                     float* __restrict__ ctx) {
    extern __shared__ float sh[];
    float* Ps = sh;                 // [64][68]
    float* Vs = sh + 64 * 68;       // [64][128]

    const int qt = blockIdx.x, h = blockIdx.y, b = blockIdx.z;
    const int kvh = h >> 2;
    const int bh = b * QHEADS + h;
    const int t = threadIdx.x;
    const int tx = t & 31;          // d-group: 4 consecutive d = tx*4
    const int ty = t >> 5;          // row-group: 8 rows = ty*8..+7

    float acc[8][4];
    #pragma unroll
    for (int i = 0; i < 8; i++)
        #pragma unroll
        for (int j = 0; j < 4; j++) acc[i][j] = 0.0f;

    for (int kt = 0; kt <= qt; kt++) {
        for (int e = t; e < 64 * 128; e += 256) {
            int r = e >> 7, d = e & 127;
            Vs[r * 128 + d] =
                V[(size_t)(b * TSZ + kt * 64 + r) * KO + kvh * HDIM + d];
        }
        for (int e = t; e < 64 * 64; e += 256) {
            int r = e >> 6, c = e & 63;
            Ps[r * 68 + c] = L[(size_t)bh * TSZ * TSZ
                               + (size_t)(qt * 64 + r) * TSZ + kt * 64 + c];
        }
        __syncthreads();

        #pragma unroll 2
        for (int kk = 0; kk < 64; kk += 4) {
            float4 v0 = *(const float4*)&Vs[(kk + 0) * 128 + tx * 4];
            float4 v1 = *(const float4*)&Vs[(kk + 1) * 128 + tx * 4];
            float4 v2 = *(const float4*)&Vs[(kk + 2) * 128 + tx * 4];
            float4 v3 = *(const float4*)&Vs[(kk + 3) * 128 + tx * 4];
            #pragma unroll
            for (int i = 0; i < 8; i++) {
                float4 pq = *(const float4*)&Ps[(ty * 8 + i) * 68 + kk];
                acc[i][0] += pq.x * v0.x + pq.y * v1.x + pq.z * v2.x + pq.w * v3.x;
                acc[i][1] += pq.x * v0.y + pq.y * v1.y + pq.z * v2.y + pq.w * v3.y;
                acc[i][2] += pq.x * v0.z + pq.y * v1.z + pq.z * v2.z + pq.w * v3.z;
                acc[i][3] += pq.x * v0.w + pq.y * v1.w + pq.z * v2.w + pq.w * v3.w;
            }
        }
        __syncthreads();
    }

    #pragma unroll
    for (int i = 0; i < 8; i++) {
        float4 o = make_float4(acc[i][0], acc[i][1], acc[i][2], acc[i][3]);
        *(float4*)(ctx + (size_t)(b * TSZ + qt * 64 + ty * 8 + i) * QO
                   + h * HDIM + tx * 4) = o;
    }
}

// ---------------------------------------------------------------------------
extern "C" void kernel_launch(void* const* d_in, const int* in_sizes, int n_in,
                              void* d_out, int out_size) {
    (void)in_sizes; (void)n_in; (void)out_size;

    // Literal setup_inputs order (proven): x, positions, wq, wk, wv, wo
    const float* x   = (const float*)d_in[0];
    const int*   pos = (const int*)  d_in[1];
    const float* wq  = (const float*)d_in[2];
    const float* wk  = (const float*)d_in[3];
    const float* wv  = (const float*)d_in[4];
    const float* wo  = (const float*)d_in[5];
    float* out = (float*)d_out;

    float *Qp, *Kp, *Vp, *Cp, *Lp;
    cudaGetSymbolAddress((void**)&Qp, g_Q);
    cudaGetSymbolAddress((void**)&Kp, g_K);
    cudaGetSymbolAddress((void**)&Vp, g_V);
    cudaGetSymbolAddress((void**)&Cp, g_ctx);
    cudaGetSymbolAddress((void**)&Lp, g_logits);

    const int TPB = 256;

    // Projections on tensor cores (bf16x3): Y = X * W^T
    gemm_bf16x3<<<dim3(QO/64, NTOK/128), TPB>>>(x, wq, Qp, QO, DMODEL);
    gemm_bf16x3<<<dim3(KO/64, NTOK/128), TPB>>>(x, wk, Kp, KO, DMODEL);
    gemm_bf16x3<<<dim3(KO/64, NTOK/128), TPB>>>(x, wv, Vp, KO, DMODEL);

    // RoPE (proven)
    naive_rope<<<(unsigned)(((long long)NTOK*QHEADS*64 + TPB-1)/TPB), TPB>>>(Qp, pos, QHEADS);
    naive_rope<<<(unsigned)(((long long)NTOK*KVHEADS*64 + TPB-1)/TPB), TPB>>>(Kp, pos, KVHEADS);

    // Attention: logits -> softmax -> P@V (proven)
    int lg_sh = 2 * 128 * 68 * (int)sizeof(float);   // 69632
    cudaFuncSetAttribute(logits_t, cudaFuncAttributeMaxDynamicSharedMemorySize, lg_sh);
    logits_t<<<dim3(TSZ/64, TSZ/64, BSZ*QHEADS), TPB, lg_sh>>>(Qp, Kp, Lp);

    int sm_sh = TSZ * (int)sizeof(float);            // 8192
    softmax_t<<<BSZ*QHEADS*TSZ, TPB, sm_sh>>>(Lp);

    int pv_sh = (64*68 + 64*128) * (int)sizeof(float);  // 50176
    cudaFuncSetAttribute(pv_t, cudaFuncAttributeMaxDynamicSharedMemorySize, pv_sh);
    pv_t<<<dim3(TSZ/64, QHEADS, BSZ), TPB, pv_sh>>>(Lp, Vp, Cp);

    // Output projection on tensor cores
    gemm_bf16x3<<<dim3(DMODEL/64, NTOK/128), TPB>>>(Cp, wo, out, DMODEL, QO);
}

// round 9
// speedup vs baseline: 83.5196x; 1.2399x over previous
#include <cuda_runtime.h>
#include <cuda_bf16.h>
#include <math.h>
#include <cstdint>

#define BSZ 2
#define TSZ 2048
#define DMODEL 2048
#define QHEADS 16
#define KVHEADS 4
#define HDIM 128
#define NTOK (BSZ*TSZ)          // 4096
#define QO (QHEADS*HDIM)        // 2048
#define KO (KVHEADS*HDIM)       // 512

// Scratch (device globals: allocation-rule-safe)
__device__ float g_Q[(size_t)NTOK*QO];
__device__ float g_K[(size_t)NTOK*KO];
__device__ float g_V[(size_t)NTOK*KO];
__device__ float g_ctx[(size_t)NTOK*QO];

// ---------------------------------------------------------------------------
// mma.sync m16n8k16 bf16 -> fp32, fragment maps validated in round 8.
// a-reg order: (r,k),(r+8,k),(r,k+8),(r+8,k+8); b: (n,k),(n,k+8);
// c: c0,c1=(r, n0+lq*2{,+1}); c2,c3=(r+8, ...).
// ---------------------------------------------------------------------------
#define MMA_BF16(d, a0,a1,a2,a3, b0,b1)                                       \
    asm volatile(                                                             \
        "mma.sync.aligned.m16n8k16.row.col.f32.bf16.bf16.f32 "                \
        "{%0,%1,%2,%3},{%4,%5,%6,%7},{%8,%9},{%0,%1,%2,%3};"                  \
        : "+f"(d[0]), "+f"(d[1]), "+f"(d[2]), "+f"(d[3])                      \
        : "r"(a0), "r"(a1), "r"(a2), "r"(a3), "r"(b0), "r"(b1))

__device__ __forceinline__ void split_bf16(float x, __nv_bfloat16& h,
                                           __nv_bfloat16& l) {
    h = __float2bfloat16(x);
    l = __float2bfloat16(x - __bfloat162float(h));
}

__device__ __forceinline__ uint32_t pack_bf16(__nv_bfloat16 a, __nv_bfloat16 b) {
    __nv_bfloat162 t = __halves2bfloat162(a, b);
    return *(uint32_t*)&t;
}

// ---------------------------------------------------------------------------
// bf16x3 tensor-core GEMM (proven round 8, unchanged): C = A * B^T.
// ---------------------------------------------------------------------------
__global__ void gemm_bf16x3(const float* __restrict__ A,
                            const float* __restrict__ B,
                            float* __restrict__ C,
                            int N, int K) {
    __shared__ __nv_bfloat16 Ah[128][18], Al[128][18];
    __shared__ __nv_bfloat16 Bh[64][18],  Bl[64][18];

    const int t    = threadIdx.x;
    const int lane = t & 31;
    const int wid  = t >> 5;
    const int wm   = wid >> 1;
    const int wn   = wid & 1;
    const int bm   = blockIdx.y * 128, bn = blockIdx.x * 64;
    const int lr   = lane >> 2;
    const int lc   = (lane & 3) * 2;

    float acc[2][4][4];
    #pragma unroll
    for (int mf = 0; mf < 2; mf++)
        #pragma unroll
        for (int nf = 0; nf < 4; nf++)
            #pragma unroll
            for (int e = 0; e < 4; e++) acc[mf][nf][e] = 0.0f;

    for (int k0 = 0; k0 < K; k0 += 16) {
        #pragma unroll
        for (int e = 0; e < 2; e++) {
            int f = t + e * 256;
            int r = f >> 2, c = (f & 3) * 4;
            float4 v = *(const float4*)(A + (size_t)(bm + r) * K + k0 + c);
            split_bf16(v.x, Ah[r][c+0], Al[r][c+0]);
            split_bf16(v.y, Ah[r][c+1], Al[r][c+1]);
            split_bf16(v.z, Ah[r][c+2], Al[r][c+2]);
            split_bf16(v.w, Ah[r][c+3], Al[r][c+3]);
        }
        {
            int r = t >> 2, c = (t & 3) * 4;
            float4 v = *(const float4*)(B + (size_t)(bn + r) * K + k0 + c);
            split_bf16(v.x, Bh[r][c+0], Bl[r][c+0]);
            split_bf16(v.y, Bh[r][c+1], Bl[r][c+1]);
            split_bf16(v.z, Bh[r][c+2], Bl[r][c+2]);
            split_bf16(v.w, Bh[r][c+3], Bl[r][c+3]);
        }
        __syncthreads();

        uint32_t bh[4][2], bl[4][2];
        #pragma unroll
        for (int nf = 0; nf < 4; nf++) {
            int n0 = wn * 32 + nf * 8 + lr;
            bh[nf][0] = *(const uint32_t*)&Bh[n0][lc];
            bh[nf][1] = *(const uint32_t*)&Bh[n0][lc + 8];
            bl[nf][0] = *(const uint32_t*)&Bl[n0][lc];
            bl[nf][1] = *(const uint32_t*)&Bl[n0][lc + 8];
        }

        #pragma unroll
        for (int mf = 0; mf < 2; mf++) {
            int m0 = wm * 32 + mf * 16 + lr;
            uint32_t ah0 = *(const uint32_t*)&Ah[m0][lc];
            uint32_t ah1 = *(const uint32_t*)&Ah[m0 + 8][lc];
            uint32_t ah2 = *(const uint32_t*)&Ah[m0][lc + 8];
            uint32_t ah3 = *(const uint32_t*)&Ah[m0 + 8][lc + 8];
            uint32_t al0 = *(const uint32_t*)&Al[m0][lc];
            uint32_t al1 = *(const uint32_t*)&Al[m0 + 8][lc];
            uint32_t al2 = *(const uint32_t*)&Al[m0][lc + 8];
            uint32_t al3 = *(const uint32_t*)&Al[m0 + 8][lc + 8];
            #pragma unroll
            for (int nf = 0; nf < 4; nf++) {
                MMA_BF16(acc[mf][nf], ah0, ah1, ah2, ah3, bh[nf][0], bh[nf][1]);
                MMA_BF16(acc[mf][nf], ah0, ah1, ah2, ah3, bl[nf][0], bl[nf][1]);
                MMA_BF16(acc[mf][nf], al0, al1, al2, al3, bh[nf][0], bh[nf][1]);
            }
        }
        __syncthreads();
    }

    #pragma unroll
    for (int mf = 0; mf < 2; mf++) {
        #pragma unroll
        for (int nf = 0; nf < 4; nf++) {
            int r0 = bm + wm * 32 + mf * 16 + lr;
            int c0 = bn + wn * 32 + nf * 8 + lc;
            *(float2*)(C + (size_t)r0 * N + c0) =
                make_float2(acc[mf][nf][0], acc[mf][nf][1]);
            *(float2*)(C + (size_t)(r0 + 8) * N + c0) =
                make_float2(acc[mf][nf][2], acc[mf][nf][3]);
        }
    }
}

// ---------------------------------------------------------------------------
// RoPE — proven, unchanged.
// ---------------------------------------------------------------------------
__global__ void naive_rope(float* __restrict__ buf,
                           const int* __restrict__ positions,
                           int nheads) {
    long long idx = (long long)blockIdx.x * blockDim.x + threadIdx.x;
    long long total = (long long)NTOK * nheads * 64;
    if (idx >= total) return;
    int i = (int)(idx % 64);
    int h = (int)((idx / 64) % nheads);
    int n = (int)(idx / (64 * nheads));
    float pos = (float)positions[n];
    float inv = powf(10000.0f, -(float)i / 64.0f);
    float ang = pos * inv;
    float c = cosf(ang);
    float s = sinf(ang);
    size_t base = ((size_t)n * nheads + h) * HDIM;
    float x1 = buf[base + i];
    float x2 = buf[base + 64 + i];
    buf[base + i]      = x1 * c - x2 * s;
    buf[base + 64 + i] = x1 * s + x2 * c;
}

// ---------------------------------------------------------------------------
// Fused flash attention, tensor cores, bf16x3 for both S=Q·K^T and O+=P·V.
// Block: 64 q-rows x 1 head x 1 batch. 4 warps (128 thr); warp owns 16 rows.
// Online softmax per row (quad shuffles). P stays in registers (C->A frag
// identity). V staged transposed [d][key] for the B fragment.
// smem (bf16): Qh/Ql[64][136], Kh/Kl[64][136], Vh/Vl[128][72]  = 104 KB.
// ---------------------------------------------------------------------------
__global__ void flash_tc(const float* __restrict__ Qg,
                         const float* __restrict__ Kg,
                         const float* __restrict__ Vg,
                         float* __restrict__ ctx) {
    extern __shared__ __nv_bfloat16 sm[];
    __nv_bfloat16* Qh = sm;
    __nv_bfloat16* Ql = Qh + 64 * 136;
    __nv_bfloat16* Kh = Ql + 64 * 136;
    __nv_bfloat16* Kl = Kh + 64 * 136;
    __nv_bfloat16* Vh = Kl + 64 * 136;
    __nv_bfloat16* Vl = Vh + 128 * 72;

    const int qt = gridDim.x - 1 - blockIdx.x;   // reversed: big blocks first
    const int h  = blockIdx.y, b = blockIdx.z;
    const int kvh = h >> 2;
    const int tid = threadIdx.x;
    const int lane = tid & 31;
    const int w    = tid >> 5;
    const int lr   = lane >> 2;        // 0..7
    const int lq   = lane & 3;         // 0..3

    // Stage Q tile once (64 x 128 fp32 -> hi/lo bf16)
    for (int i = tid; i < 2048; i += 128) {
        int r = i >> 5, c4 = (i & 31) * 4;
        float4 v = *(const float4*)(Qg + (size_t)(b * TSZ + qt * 64 + r) * QO
                                    + h * HDIM + c4);
        split_bf16(v.x, Qh[r*136 + c4+0], Ql[r*136 + c4+0]);
        split_bf16(v.y, Qh[r*136 + c4+1], Ql[r*136 + c4+1]);
        split_bf16(v.z, Qh[r*136 + c4+2], Ql[r*136 + c4+2]);
        split_bf16(v.w, Qh[r*136 + c4+3], Ql[r*136 + c4+3]);
    }

    float m0 = -1e30f, m1 = -1e30f, l0 = 0.0f, l1 = 0.0f;
    float Oacc[16][4];
    #pragma unroll
    for (int nf = 0; nf < 16; nf++)
        #pragma unroll
        for (int e = 0; e < 4; e++) Oacc[nf][e] = 0.0f;

    const int qrow0 = qt * 64 + w * 16 + lr;   // global q row for c0,c1
    const float sc = 0.08838834764831845f;     // 1/sqrt(128)

    for (int kt = 0; kt <= qt; kt++) {
        __syncthreads();   // Q staged (iter 0) / prior K,V reads done

        // Stage K tile (64 keys x 128 d)
        for (int i = tid; i < 2048; i += 128) {
            int r = i >> 5, c4 = (i & 31) * 4;
            float4 v = *(const float4*)(Kg + (size_t)(b * TSZ + kt * 64 + r) * KO
                                        + kvh * HDIM + c4);
            split_bf16(v.x, Kh[r*136 + c4+0], Kl[r*136 + c4+0]);
            split_bf16(v.y, Kh[r*136 + c4+1], Kl[r*136 + c4+1]);
            split_bf16(v.z, Kh[r*136 + c4+2], Kl[r*136 + c4+2]);
            split_bf16(v.w, Kh[r*136 + c4+3], Kl[r*136 + c4+3]);
        }
        // Stage V transposed: Vs[d][key]
        for (int i = tid; i < 2048; i += 128) {
            int r = i >> 5, c4 = (i & 31) * 4;
            float4 v = *(const float4*)(Vg + (size_t)(b * TSZ + kt * 64 + r) * KO
                                        + kvh * HDIM + c4);
            split_bf16(v.x, Vh[(c4+0)*72 + r], Vl[(c4+0)*72 + r]);
            split_bf16(v.y, Vh[(c4+1)*72 + r], Vl[(c4+1)*72 + r]);
            split_bf16(v.z, Vh[(c4+2)*72 + r], Vl[(c4+2)*72 + r]);
            split_bf16(v.w, Vh[(c4+3)*72 + r], Vl[(c4+3)*72 + r]);
        }
        __syncthreads();

        // ---- S = Q . K^T (bf16x3), warp tile 16x64 ----
        float sacc[8][4];
        #pragma unroll
        for (int nf = 0; nf < 8; nf++)
            #pragma unroll
            for (int e = 0; e < 4; e++) sacc[nf][e] = 0.0f;

        #pragma unroll
        for (int kk = 0; kk < 8; kk++) {
            int qr = w * 16 + lr;
            int kc = kk * 16 + lq * 2;
            uint32_t ah0 = *(const uint32_t*)&Qh[qr*136 + kc];
            uint32_t ah1 = *(const uint32_t*)&Qh[(qr+8)*136 + kc];
            uint32_t ah2 = *(const uint32_t*)&Qh[qr*136 + kc + 8];
            uint32_t ah3 = *(const uint32_t*)&Qh[(qr+8)*136 + kc + 8];
            uint32_t al0 = *(const uint32_t*)&Ql[qr*136 + kc];
            uint32_t al1 = *(const uint32_t*)&Ql[(qr+8)*136 + kc];
            uint32_t al2 = *(const uint32_t*)&Ql[qr*136 + kc + 8];
            uint32_t al3 = *(const uint32_t*)&Ql[(qr+8)*136 + kc + 8];
            #pragma unroll
            for (int nf = 0; nf < 8; nf++) {
                int n0 = nf * 8 + lr;
                uint32_t bh0 = *(const uint32_t*)&Kh[n0*136 + kc];
                uint32_t bh1 = *(const uint32_t*)&Kh[n0*136 + kc + 8];
                uint32_t bl0 = *(const uint32_t*)&Kl[n0*136 + kc];
                uint32_t bl1 = *(const uint32_t*)&Kl[n0*136 + kc + 8];
                MMA_BF16(sacc[nf], ah0, ah1, ah2, ah3, bh0, bh1);
                MMA_BF16(sacc[nf], ah0, ah1, ah2, ah3, bl0, bl1);
                MMA_BF16(sacc[nf], al0, al1, al2, al3, bh0, bh1);
            }
        }

        // ---- scale + causal mask ----
        const bool diag = (kt == qt);
        #pragma unroll
        for (int nf = 0; nf < 8; nf++) {
            int nc = kt * 64 + nf * 8 + lq * 2;
            sacc[nf][0] *= sc; sacc[nf][1] *= sc;
            sacc[nf][2] *= sc; sacc[nf][3] *= sc;
            if (diag) {
                if (nc     > qrow0)     sacc[nf][0] = -1e9f;
                if (nc + 1 > qrow0)     sacc[nf][1] = -1e9f;
                if (nc     > qrow0 + 8) sacc[nf][2] = -1e9f;
                if (nc + 1 > qrow0 + 8) sacc[nf][3] = -1e9f;
            }
        }

        // ---- online softmax: row max (quad reduce) ----
        float tm0 = -1e30f, tm1 = -1e30f;
        #pragma unroll
        for (int nf = 0; nf < 8; nf++) {
            tm0 = fmaxf(tm0, fmaxf(sacc[nf][0], sacc[nf][1]));
            tm1 = fmaxf(tm1, fmaxf(sacc[nf][2], sacc[nf][3]));
        }
        tm0 = fmaxf(tm0, __shfl_xor_sync(0xffffffffu, tm0, 1));
        tm0 = fmaxf(tm0, __shfl_xor_sync(0xffffffffu, tm0, 2));
        tm1 = fmaxf(tm1, __shfl_xor_sync(0xffffffffu, tm1, 1));
        tm1 = fmaxf(tm1, __shfl_xor_sync(0xffffffffu, tm1, 2));

        float mn0 = fmaxf(m0, tm0), mn1 = fmaxf(m1, tm1);
        float al_0 = __expf(m0 - mn0), al_1 = __expf(m1 - mn1);
        m0 = mn0; m1 = mn1;

        // ---- P = exp(S - m); pack into A fragments; row sums ----
        uint32_t paH[4][4], paL[4][4];
        float rs0 = 0.0f, rs1 = 0.0f;
        #pragma unroll
        for (int nf = 0; nf < 8; nf++) {
            float p0 = __expf(sacc[nf][0] - m0);
            float p1 = __expf(sacc[nf][1] - m0);
            float p2 = __expf(sacc[nf][2] - m1);
            float p3 = __expf(sacc[nf][3] - m1);
            rs0 += p0 + p1; rs1 += p2 + p3;
            __nv_bfloat16 h0, l0b, h1, l1b, h2, l2b, h3, l3b;
            split_bf16(p0, h0, l0b); split_bf16(p1, h1, l1b);
            split_bf16(p2, h2, l2b); split_bf16(p3, h3, l3b);
            int kk = nf >> 1, half = nf & 1;
            paH[kk][half*2 + 0] = pack_bf16(h0, h1);
            paH[kk][half*2 + 1] = pack_bf16(h2, h3);
            paL[kk][half*2 + 0] = pack_bf16(l0b, l1b);
            paL[kk][half*2 + 1] = pack_bf16(l2b, l3b);
        }
        rs0 += __shfl_xor_sync(0xffffffffu, rs0, 1);
        rs0 += __shfl_xor_sync(0xffffffffu, rs0, 2);
        rs1 += __shfl_xor_sync(0xffffffffu, rs1, 1);
        rs1 += __shfl_xor_sync(0xffffffffu, rs1, 2);
        l0 = l0 * al_0 + rs0;
        l1 = l1 * al_1 + rs1;

        // ---- rescale O ----
        #pragma unroll
        for (int nf = 0; nf < 16; nf++) {
            Oacc[nf][0] *= al_0; Oacc[nf][1] *= al_0;
            Oacc[nf][2] *= al_1; Oacc[nf][3] *= al_1;
        }

        // ---- O += P . V (bf16x3) ----
        #pragma unroll
        for (int kk = 0; kk < 4; kk++) {
            int kc = kk * 16 + lq * 2;
            #pragma unroll
            for (int nf = 0; nf < 16; nf++) {
                int n0 = nf * 8 + lr;
                uint32_t bh0 = *(const uint32_t*)&Vh[n0*72 + kc];
                uint32_t bh1 = *(const uint32_t*)&Vh[n0*72 + kc + 8];
                uint32_t bl0 = *(const uint32_t*)&Vl[n0*72 + kc];
                uint32_t bl1 = *(const uint32_t*)&Vl[n0*72 + kc + 8];
                MMA_BF16(Oacc[nf], paH[kk][0], paH[kk][1], paH[kk][2], paH[kk][3], bh0, bh1);
                MMA_BF16(Oacc[nf], paH[kk][0], paH[kk][1], paH[kk][2], paH[kk][3], bl0, bl1);
                MMA_BF16(Oacc[nf], paL[kk][0], paL[kk][1], paL[kk][2], paL[kk][3], bh0, bh1);
            }
        }
    }

    // ---- normalize + write ctx ----
    float inv0 = 1.0f / l0, inv1 = 1.0f / l1;
    #pragma unroll
    for (int nf = 0; nf < 16; nf++) {
        size_t g0 = (size_t)(b * TSZ + qt * 64 + w * 16 + lr) * QO
                    + h * HDIM + nf * 8 + lq * 2;
        *(float2*)(ctx + g0) = make_float2(Oacc[nf][0] * inv0, Oacc[nf][1] * inv0);
        *(float2*)(ctx + g0 + (size_t)8 * QO) =
            make_float2(Oacc[nf][2] * inv1, Oacc[nf][3] * inv1);
    }
}

// ---------------------------------------------------------------------------
extern "C" void kernel_launch(void* const* d_in, const int* in_sizes, int n_in,
                              void* d_out, int out_size) {
    (void)in_sizes; (void)n_in; (void)out_size;

    // Literal setup_inputs order (proven): x, positions, wq, wk, wv, wo
    const float* x   = (const float*)d_in[0];
    const int*   pos = (const int*)  d_in[1];
    const float* wq  = (const float*)d_in[2];
    const float* wk  = (const float*)d_in[3];
    const float* wv  = (const float*)d_in[4];
    const float* wo  = (const float*)d_in[5];
    float* out = (float*)d_out;

    float *Qp, *Kp, *Vp, *Cp;
    cudaGetSymbolAddress((void**)&Qp, g_Q);
    cudaGetSymbolAddress((void**)&Kp, g_K);
    cudaGetSymbolAddress((void**)&Vp, g_V);
    cudaGetSymbolAddress((void**)&Cp, g_ctx);

    const int TPB = 256;

    // Projections on tensor cores (bf16x3): Y = X * W^T
    gemm_bf16x3<<<dim3(QO/64, NTOK/128), TPB>>>(x, wq, Qp, QO, DMODEL);
    gemm_bf16x3<<<dim3(KO/64, NTOK/128), TPB>>>(x, wk, Kp, KO, DMODEL);
    gemm_bf16x3<<<dim3(KO/64, NTOK/128), TPB>>>(x, wv, Vp, KO, DMODEL);

    // RoPE (proven)
    naive_rope<<<(unsigned)(((long long)NTOK*QHEADS*64 + TPB-1)/TPB), TPB>>>(Qp, pos, QHEADS);
    naive_rope<<<(unsigned)(((long long)NTOK*KVHEADS*64 + TPB-1)/TPB), TPB>>>(Kp, pos, KVHEADS);

    // Fused flash attention on tensor cores
    int fl_sh = (4 * 64 * 136 + 2 * 128 * 72) * (int)sizeof(__nv_bfloat16); // 106496
    cudaFuncSetAttribute(flash_tc, cudaFuncAttributeMaxDynamicSharedMemorySize, fl_sh);
    flash_tc<<<dim3(TSZ/64, QHEADS, BSZ), 128, fl_sh>>>(Qp, Kp, Vp, Cp);

    // Output projection on tensor cores
    gemm_bf16x3<<<dim3(DMODEL/64, NTOK/128), TPB>>>(Cp, wo, out, DMODEL, QO);
}

// round 12
// speedup vs baseline: 152.8610x; 1.8302x over previous
#include <cuda_runtime.h>
#include <cuda_bf16.h>
#include <math.h>
#include <cstdint>

#define BSZ 2
#define TSZ 2048
#define DMODEL 2048
#define QHEADS 16
#define KVHEADS 4
#define HDIM 128
#define NTOK (BSZ*TSZ)          // 4096
#define QO (QHEADS*HDIM)        // 2048
#define KO (KVHEADS*HDIM)       // 512

// ---------------- persistent scratch (allocation-rule-safe) ----------------
__device__ float g_Q[(size_t)NTOK*QO];
__device__ float g_K[(size_t)NTOK*KO];
__device__ float g_V[(size_t)NTOK*KO];
__device__ float g_ctx[(size_t)NTOK*QO];

__device__ __nv_bfloat16 g_xh[(size_t)NTOK*DMODEL],  g_xl[(size_t)NTOK*DMODEL];
__device__ __nv_bfloat16 g_wqh[(size_t)QO*DMODEL],   g_wql[(size_t)QO*DMODEL];
__device__ __nv_bfloat16 g_wkh[(size_t)KO*DMODEL],   g_wkl[(size_t)KO*DMODEL];
__device__ __nv_bfloat16 g_wvh[(size_t)KO*DMODEL],   g_wvl[(size_t)KO*DMODEL];
__device__ __nv_bfloat16 g_woh[(size_t)DMODEL*QO],   g_wol[(size_t)DMODEL*QO];
__device__ __nv_bfloat16 g_Qh[(size_t)NTOK*QO],      g_Ql[(size_t)NTOK*QO];
__device__ __nv_bfloat16 g_Kh[(size_t)NTOK*KO],      g_Kl[(size_t)NTOK*KO];
__device__ __nv_bfloat16 g_Vth[(size_t)NTOK*KO],     g_Vtl[(size_t)NTOK*KO]; // [b][kvh][d][T]
__device__ __nv_bfloat16 g_ch[(size_t)NTOK*QO],      g_cl[(size_t)NTOK*QO];

// ---------------- helpers ----------------
#define MMA_BF16(d, a0,a1,a2,a3, b0,b1)                                       \
    asm volatile(                                                             \
        "mma.sync.aligned.m16n8k16.row.col.f32.bf16.bf16.f32 "                \
        "{%0,%1,%2,%3},{%4,%5,%6,%7},{%8,%9},{%0,%1,%2,%3};"                  \
        : "+f"(d[0]), "+f"(d[1]), "+f"(d[2]), "+f"(d[3])                      \
        : "r"(a0), "r"(a1), "r"(a2), "r"(a3), "r"(b0), "r"(b1))

__device__ __forceinline__ void split_bf16(float x, __nv_bfloat16& h,
                                           __nv_bfloat16& l) {
    h = __float2bfloat16(x);
    l = __float2bfloat16(x - __bfloat162float(h));
}

__device__ __forceinline__ uint32_t pack_bf16(__nv_bfloat16 a, __nv_bfloat16 b) {
    __nv_bfloat162 t = __halves2bfloat162(a, b);
    return *(uint32_t*)&t;
}

__device__ __forceinline__ void cp16(void* dst_smem, const void* src) {
    uint32_t d = (uint32_t)__cvta_generic_to_shared(dst_smem);
    asm volatile("cp.async.cg.shared.global [%0], [%1], 16;" :: "r"(d), "l"(src));
}
#define CP_COMMIT() asm volatile("cp.async.commit_group;")
#define CP_WAIT(n)  asm volatile("cp.async.wait_group %0;" :: "n"(n))

// ---------------- split kernels ----------------
__global__ void split_arr(const float* __restrict__ src,
                          __nv_bfloat16* __restrict__ h,
                          __nv_bfloat16* __restrict__ l, long long n4) {
    long long i = (long long)blockIdx.x * blockDim.x + threadIdx.x;
    if (i >= n4) return;
    float4 v = *(const float4*)(src + i * 4);
    __nv_bfloat16 h0,l0,h1,l1,h2,l2,h3,l3;
    split_bf16(v.x, h0, l0); split_bf16(v.y, h1, l1);
    split_bf16(v.z, h2, l2); split_bf16(v.w, h3, l3);
    ((__nv_bfloat162*)h)[i*2]   = __halves2bfloat162(h0, h1);
    ((__nv_bfloat162*)h)[i*2+1] = __halves2bfloat162(h2, h3);
    ((__nv_bfloat162*)l)[i*2]   = __halves2bfloat162(l0, l1);
    ((__nv_bfloat162*)l)[i*2+1] = __halves2bfloat162(l2, l3);
}

// RoPE + split (reads raw fp32 proj, writes rotated bf16 hi/lo).
__global__ void rope_split(const float* __restrict__ buf,
                           const int* __restrict__ positions,
                           __nv_bfloat16* __restrict__ oh,
                           __nv_bfloat16* __restrict__ ol, int nheads) {
    long long idx = (long long)blockIdx.x * blockDim.x + threadIdx.x;
    long long total = (long long)NTOK * nheads * 64;
    if (idx >= total) return;
    int i = (int)(idx % 64);
    int h = (int)((idx / 64) % nheads);
    int n = (int)(idx / (64 * nheads));
    float pos = (float)positions[n];
    float inv = powf(10000.0f, -(float)i / 64.0f);
    float c = cosf(pos * inv), s = sinf(pos * inv);
    size_t base = ((size_t)n * nheads + h) * HDIM;
    float x1 = buf[base + i], x2 = buf[base + 64 + i];
    float y1 = x1 * c - x2 * s, y2 = x1 * s + x2 * c;
    split_bf16(y1, oh[base + i], ol[base + i]);
    split_bf16(y2, oh[base + 64 + i], ol[base + 64 + i]);
}

// V transpose + split: out[((b*KVH+kvh)*128 + d)*TSZ + t] = V[(b*TSZ+t)*KO + kvh*128 + d]
__global__ void vtrans_split(const float* __restrict__ V,
                             __nv_bfloat16* __restrict__ oh,
                             __nv_bfloat16* __restrict__ ol) {
    long long idx = (long long)blockIdx.x * blockDim.x + threadIdx.x;
    long long total = (long long)NTOK * KO;
    if (idx >= total) return;
    int t  = (int)(idx % TSZ);
    int d  = (int)((idx / TSZ) % HDIM);
    int kvh = (int)((idx / ((long long)TSZ * HDIM)) % KVHEADS);
    int b  = (int)(idx / ((long long)TSZ * HDIM * KVHEADS));
    float v = V[(size_t)(b * TSZ + t) * KO + kvh * HDIM + d];
    split_bf16(v, oh[idx], ol[idx]);
}

// ---------------------------------------------------------------------------
// Pipelined bf16x3 GEMM on pre-split operands: C[M,N] = A[M,K]*B[N,K]^T.
// 128x128 block tile, BK=32, 256 thr (8 warps as 4Mx2N, warp tile 32x64),
// 2-stage cp.async double buffer. Requires M%128==N%128==0, K%32==0.
// ---------------------------------------------------------------------------
__global__ void gemm_sp(const __nv_bfloat16* __restrict__ Ahg,
                        const __nv_bfloat16* __restrict__ Alg,
                        const __nv_bfloat16* __restrict__ Bhg,
                        const __nv_bfloat16* __restrict__ Blg,
                        float* __restrict__ C, int N, int K) {
    extern __shared__ __nv_bfloat16 S[];   // [2 stages][4 bufs][128*40]
    const int t    = threadIdx.x;
    const int lane = t & 31;
    const int wid  = t >> 5;
    const int wm   = wid >> 1;            // 0..3
    const int wn   = wid & 1;             // 0..1
    const int bm   = blockIdx.y * 128, bn = blockIdx.x * 128;
    const int lr   = lane >> 2;
    const int lq   = lane & 3;
    const int lc   = lq * 2;

    float acc[2][8][4];
    #pragma unroll
    for (int mf = 0; mf < 2; mf++)
        #pragma unroll
        for (int nf = 0; nf < 8; nf++)
            #pragma unroll
            for (int e = 0; e < 4; e++) acc[mf][nf][e] = 0.0f;

    const int KT = K / 32;
    auto load_stage = [&](int st, int k0) {
        __nv_bfloat16* ah = S + (st*4 + 0) * (128*40);
        __nv_bfloat16* al = S + (st*4 + 1) * (128*40);
        __nv_bfloat16* bh = S + (st*4 + 2) * (128*40);
        __nv_bfloat16* bl = S + (st*4 + 3) * (128*40);
        #pragma unroll
        for (int e = 0; e < 2; e++) {
            int cid = e * 256 + t;
            int r = cid >> 2, c8 = (cid & 3) * 8;
            cp16(ah + r*40 + c8, Ahg + (size_t)(bm + r) * K + k0 + c8);
            cp16(al + r*40 + c8, Alg + (size_t)(bm + r) * K + k0 + c8);
            cp16(bh + r*40 + c8, Bhg + (size_t)(bn + r) * K + k0 + c8);
            cp16(bl + r*40 + c8, Blg + (size_t)(bn + r) * K + k0 + c8);
        }
        CP_COMMIT();
    };

    load_stage(0, 0);

    for (int kt = 0; kt < KT; kt++) {
        if (kt + 1 < KT) load_stage((kt + 1) & 1, (kt + 1) * 32);
        if (kt + 1 < KT) { CP_WAIT(1); } else { CP_WAIT(0); }
        __syncthreads();

        const int st = kt & 1;
        const __nv_bfloat16* ah = S + (st*4 + 0) * (128*40);
        const __nv_bfloat16* al = S + (st*4 + 1) * (128*40);
        const __nv_bfloat16* bh = S + (st*4 + 2) * (128*40);
        const __nv_bfloat16* bl = S + (st*4 + 3) * (128*40);

        #pragma unroll
        for (int k16 = 0; k16 < 2; k16++) {
            int kc = k16 * 16 + lc;
            // B fragments (8 n-frags x {hi,lo})
            uint32_t Bh[8][2], Bl[8][2];
            #pragma unroll
            for (int nf = 0; nf < 8; nf++) {
                int n0 = wn * 64 + nf * 8 + lr;
                Bh[nf][0] = *(const uint32_t*)&bh[n0*40 + kc];
                Bh[nf][1] = *(const uint32_t*)&bh[n0*40 + kc + 8];
                Bl[nf][0] = *(const uint32_t*)&bl[n0*40 + kc];
                Bl[nf][1] = *(const uint32_t*)&bl[n0*40 + kc + 8];
            }
            #pragma unroll
            for (int mf = 0; mf < 2; mf++) {
                int m0 = wm * 32 + mf * 16 + lr;
                uint32_t ah0 = *(const uint32_t*)&ah[m0*40 + kc];
                uint32_t ah1 = *(const uint32_t*)&ah[(m0+8)*40 + kc];
                uint32_t ah2 = *(const uint32_t*)&ah[m0*40 + kc + 8];
                uint32_t ah3 = *(const uint32_t*)&ah[(m0+8)*40 + kc + 8];
                uint32_t al0 = *(const uint32_t*)&al[m0*40 + kc];
                uint32_t al1 = *(const uint32_t*)&al[(m0+8)*40 + kc];
                uint32_t al2 = *(const uint32_t*)&al[m0*40 + kc + 8];
                uint32_t al3 = *(const uint32_t*)&al[(m0+8)*40 + kc + 8];
                #pragma unroll
                for (int nf = 0; nf < 8; nf++) {
                    MMA_BF16(acc[mf][nf], ah0, ah1, ah2, ah3, Bh[nf][0], Bh[nf][1]);
                    MMA_BF16(acc[mf][nf], ah0, ah1, ah2, ah3, Bl[nf][0], Bl[nf][1]);
                    MMA_BF16(acc[mf][nf], al0, al1, al2, al3, Bh[nf][0], Bh[nf][1]);
                }
            }
        }
        __syncthreads();
    }

    #pragma unroll
    for (int mf = 0; mf < 2; mf++) {
        #pragma unroll
        for (int nf = 0; nf < 8; nf++) {
            int r0 = bm + wm * 32 + mf * 16 + lr;
            int c0 = bn + wn * 64 + nf * 8 + lc;
            *(float2*)(C + (size_t)r0 * N + c0) =
                make_float2(acc[mf][nf][0], acc[mf][nf][1]);
            *(float2*)(C + (size_t)(r0 + 8) * N + c0) =
                make_float2(acc[mf][nf][2], acc[mf][nf][3]);
        }
    }
}

// ---------------------------------------------------------------------------
// Fused flash attention on tensor cores (round-9 compute core, pre-split I/O).
// Block: 64 q-rows x head x batch, 128 thr. smem bf16: Qh/Ql/Kh/Kl[64][136],
// Vh/Vl[128][72] = 104 KB.
// ---------------------------------------------------------------------------
__global__ void flash_tc(const __nv_bfloat16* __restrict__ Qhg,
                         const __nv_bfloat16* __restrict__ Qlg,
                         const __nv_bfloat16* __restrict__ Khg,
                         const __nv_bfloat16* __restrict__ Klg,
                         const __nv_bfloat16* __restrict__ Vhg,
                         const __nv_bfloat16* __restrict__ Vlg,
                         float* __restrict__ ctx) {
    extern __shared__ __nv_bfloat16 sm[];
    __nv_bfloat16* Qh = sm;
    __nv_bfloat16* Ql = Qh + 64 * 136;
    __nv_bfloat16* Kh = Ql + 64 * 136;
    __nv_bfloat16* Kl = Kh + 64 * 136;
    __nv_bfloat16* Vh = Kl + 64 * 136;
    __nv_bfloat16* Vl = Vh + 128 * 72;

    const int qt = gridDim.x - 1 - blockIdx.x;
    const int h  = blockIdx.y, b = blockIdx.z;
    const int kvh = h >> 2;
    const int tid = threadIdx.x;
    const int lane = tid & 31;
    const int w    = tid >> 5;
    const int lr   = lane >> 2;
    const int lq   = lane & 3;

    // Stage Q (hi+lo): 64x128 bf16 each = 1024 uint4 per buffer
    for (int cid = tid; cid < 1024; cid += 128) {
        int r = cid >> 4, c8 = (cid & 15) * 8;
        size_t g = (size_t)(b * TSZ + qt * 64 + r) * QO + h * HDIM + c8;
        *(uint4*)&Qh[r*136 + c8] = *(const uint4*)(Qhg + g);
        *(uint4*)&Ql[r*136 + c8] = *(const uint4*)(Qlg + g);
    }

    float m0 = -1e30f, m1 = -1e30f, l0 = 0.0f, l1 = 0.0f;
    float Oacc[16][4];
    #pragma unroll
    for (int nf = 0; nf < 16; nf++)
        #pragma unroll
        for (int e = 0; e < 4; e++) Oacc[nf][e] = 0.0f;

    const int qrow0 = qt * 64 + w * 16 + lr;
    const float sc = 0.08838834764831845f;

    for (int kt = 0; kt <= qt; kt++) {
        __syncthreads();

        // Stage K (64 keys x 128 d)
        for (int cid = tid; cid < 1024; cid += 128) {
            int r = cid >> 4, c8 = (cid & 15) * 8;
            size_t g = (size_t)(b * TSZ + kt * 64 + r) * KO + kvh * HDIM + c8;
            *(uint4*)&Kh[r*136 + c8] = *(const uint4*)(Khg + g);
            *(uint4*)&Kl[r*136 + c8] = *(const uint4*)(Klg + g);
        }
        // Stage V from pre-transposed [d][T]: 128 d x 64 keys
        for (int cid = tid; cid < 1024; cid += 128) {
            int d = cid >> 3, k8 = (cid & 7) * 8;
            size_t g = ((size_t)(b * KVHEADS + kvh) * HDIM + d) * TSZ + kt * 64 + k8;
            *(uint4*)&Vh[d*72 + k8] = *(const uint4*)(Vhg + g);
            *(uint4*)&Vl[d*72 + k8] = *(const uint4*)(Vlg + g);
        }
        __syncthreads();

        // ---- S = Q . K^T (bf16x3) ----
        float sacc[8][4];
        #pragma unroll
        for (int nf = 0; nf < 8; nf++)
            #pragma unroll
            for (int e = 0; e < 4; e++) sacc[nf][e] = 0.0f;

        #pragma unroll
        for (int kk = 0; kk < 8; kk++) {
            int qr = w * 16 + lr;
            int kc = kk * 16 + lq * 2;
            uint32_t ah0 = *(const uint32_t*)&Qh[qr*136 + kc];
            uint32_t ah1 = *(const uint32_t*)&Qh[(qr+8)*136 + kc];
            uint32_t ah2 = *(const uint32_t*)&Qh[qr*136 + kc + 8];
            uint32_t ah3 = *(const uint32_t*)&Qh[(qr+8)*136 + kc + 8];
            uint32_t al0 = *(const uint32_t*)&Ql[qr*136 + kc];
            uint32_t al1 = *(const uint32_t*)&Ql[(qr+8)*136 + kc];
            uint32_t al2 = *(const uint32_t*)&Ql[qr*136 + kc + 8];
            uint32_t al3 = *(const uint32_t*)&Ql[(qr+8)*136 + kc + 8];
            #pragma unroll
            for (int nf = 0; nf < 8; nf++) {
                int n0 = nf * 8 + lr;
                uint32_t bh0 = *(const uint32_t*)&Kh[n0*136 + kc];
                uint32_t bh1 = *(const uint32_t*)&Kh[n0*136 + kc + 8];
                uint32_t bl0 = *(const uint32_t*)&Kl[n0*136 + kc];
                uint32_t bl1 = *(const uint32_t*)&Kl[n0*136 + kc + 8];
                MMA_BF16(sacc[nf], ah0, ah1, ah2, ah3, bh0, bh1);
                MMA_BF16(sacc[nf], ah0, ah1, ah2, ah3, bl0, bl1);
                MMA_BF16(sacc[nf], al0, al1, al2, al3, bh0, bh1);
            }
        }

        // ---- scale + causal mask ----
        const bool diag = (kt == qt);
        #pragma unroll
        for (int nf = 0; nf < 8; nf++) {
            int nc = kt * 64 + nf * 8 + lq * 2;
            sacc[nf][0] *= sc; sacc[nf][1] *= sc;
            sacc[nf][2] *= sc; sacc[nf][3] *= sc;
            if (diag) {
                if (nc     > qrow0)     sacc[nf][0] = -1e9f;
                if (nc + 1 > qrow0)     sacc[nf][1] = -1e9f;
                if (nc     > qrow0 + 8) sacc[nf][2] = -1e9f;
                if (nc + 1 > qrow0 + 8) sacc[nf][3] = -1e9f;
            }
        }

        // ---- online softmax ----
        float tm0 = -1e30f, tm1 = -1e30f;
        #pragma unroll
        for (int nf = 0; nf < 8; nf++) {
            tm0 = fmaxf(tm0, fmaxf(sacc[nf][0], sacc[nf][1]));
            tm1 = fmaxf(tm1, fmaxf(sacc[nf][2], sacc[nf][3]));
        }
        tm0 = fmaxf(tm0, __shfl_xor_sync(0xffffffffu, tm0, 1));
        tm0 = fmaxf(tm0, __shfl_xor_sync(0xffffffffu, tm0, 2));
        tm1 = fmaxf(tm1, __shfl_xor_sync(0xffffffffu, tm1, 1));
        tm1 = fmaxf(tm1, __shfl_xor_sync(0xffffffffu, tm1, 2));

        float mn0 = fmaxf(m0, tm0), mn1 = fmaxf(m1, tm1);
        float al_0 = __expf(m0 - mn0), al_1 = __expf(m1 - mn1);
        m0 = mn0; m1 = mn1;

        uint32_t paH[4][4], paL[4][4];
        float rs0 = 0.0f, rs1 = 0.0f;
        #pragma unroll
        for (int nf = 0; nf < 8; nf++) {
            float p0 = __expf(sacc[nf][0] - m0);
            float p1 = __expf(sacc[nf][1] - m0);
            float p2 = __expf(sacc[nf][2] - m1);
            float p3 = __expf(sacc[nf][3] - m1);
            rs0 += p0 + p1; rs1 += p2 + p3;
            __nv_bfloat16 h0, l0b, h1, l1b, h2, l2b, h3, l3b;
            split_bf16(p0, h0, l0b); split_bf16(p1, h1, l1b);
            split_bf16(p2, h2, l2b); split_bf16(p3, h3, l3b);
            int kk = nf >> 1, half = nf & 1;
            paH[kk][half*2 + 0] = pack_bf16(h0, h1);
            paH[kk][half*2 + 1] = pack_bf16(h2, h3);
            paL[kk][half*2 + 0] = pack_bf16(l0b, l1b);
            paL[kk][half*2 + 1] = pack_bf16(l2b, l3b);
        }
        rs0 += __shfl_xor_sync(0xffffffffu, rs0, 1);
        rs0 += __shfl_xor_sync(0xffffffffu, rs0, 2);
        rs1 += __shfl_xor_sync(0xffffffffu, rs1, 1);
        rs1 += __shfl_xor_sync(0xffffffffu, rs1, 2);
        l0 = l0 * al_0 + rs0;
        l1 = l1 * al_1 + rs1;

        #pragma unroll
        for (int nf = 0; nf < 16; nf++) {
            Oacc[nf][0] *= al_0; Oacc[nf][1] *= al_0;
            Oacc[nf][2] *= al_1; Oacc[nf][3] *= al_1;
        }

        // ---- O += P . V (bf16x3) ----
        #pragma unroll
        for (int kk = 0; kk < 4; kk++) {
            int kc = kk * 16 + lq * 2;
            #pragma unroll
            for (int nf = 0; nf < 16; nf++) {
                int n0 = nf * 8 + lr;
                uint32_t bh0 = *(const uint32_t*)&Vh[n0*72 + kc];
                uint32_t bh1 = *(const uint32_t*)&Vh[n0*72 + kc + 8];
                uint32_t bl0 = *(const uint32_t*)&Vl[n0*72 + kc];
                uint32_t bl1 = *(const uint32_t*)&Vl[n0*72 + kc + 8];
                MMA_BF16(Oacc[nf], paH[kk][0], paH[kk][1], paH[kk][2], paH[kk][3], bh0, bh1);
                MMA_BF16(Oacc[nf], paH[kk][0], paH[kk][1], paH[kk][2], paH[kk][3], bl0, bl1);
                MMA_BF16(Oacc[nf], paL[kk][0], paL[kk][1], paL[kk][2], paL[kk][3], bh0, bh1);
            }
        }
    }

    float inv0 = 1.0f / l0, inv1 = 1.0f / l1;
    #pragma unroll
    for (int nf = 0; nf < 16; nf++) {
        size_t g0 = (size_t)(b * TSZ + qt * 64 + w * 16 + lr) * QO
                    + h * HDIM + nf * 8 + lq * 2;
        *(float2*)(ctx + g0) = make_float2(Oacc[nf][0] * inv0, Oacc[nf][1] * inv0);
        *(float2*)(ctx + g0 + (size_t)8 * QO) =
            make_float2(Oacc[nf][2] * inv1, Oacc[nf][3] * inv1);
    }
}

// ---------------------------------------------------------------------------
extern "C" void kernel_launch(void* const* d_in, const int* in_sizes, int n_in,
                              void* d_out, int out_size) {
    (void)in_sizes; (void)n_in; (void)out_size;

    const float* x   = (const float*)d_in[0];
    const int*   pos = (const int*)  d_in[1];
    const float* wq  = (const float*)d_in[2];
    const float* wk  = (const float*)d_in[3];
    const float* wv  = (const float*)d_in[4];
    const float* wo  = (const float*)d_in[5];
    float* out = (float*)d_out;

    float *Qp, *Kp, *Vp, *Cp;
    __nv_bfloat16 *xh,*xl,*wqh,*wql,*wkh,*wkl,*wvh,*wvl,*woh,*wol;
    __nv_bfloat16 *Qhp,*Qlp,*Khp,*Klp,*Vth,*Vtl,*ch,*cl;
    cudaGetSymbolAddress((void**)&Qp, g_Q);
    cudaGetSymbolAddress((void**)&Kp, g_K);
    cudaGetSymbolAddress((void**)&Vp, g_V);
    cudaGetSymbolAddress((void**)&Cp, g_ctx);
    cudaGetSymbolAddress((void**)&xh, g_xh);  cudaGetSymbolAddress((void**)&xl, g_xl);
    cudaGetSymbolAddress((void**)&wqh, g_wqh); cudaGetSymbolAddress((void**)&wql, g_wql);
    cudaGetSymbolAddress((void**)&wkh, g_wkh); cudaGetSymbolAddress((void**)&wkl, g_wkl);
    cudaGetSymbolAddress((void**)&wvh, g_wvh); cudaGetSymbolAddress((void**)&wvl, g_wvl);
    cudaGetSymbolAddress((void**)&woh, g_woh); cudaGetSymbolAddress((void**)&wol, g_wol);
    cudaGetSymbolAddress((void**)&Qhp, g_Qh);  cudaGetSymbolAddress((void**)&Qlp, g_Ql);
    cudaGetSymbolAddress((void**)&Khp, g_Kh);  cudaGetSymbolAddress((void**)&Klp, g_Kl);
    cudaGetSymbolAddress((void**)&Vth, g_Vth); cudaGetSymbolAddress((void**)&Vtl, g_Vtl);
    cudaGetSymbolAddress((void**)&ch, g_ch);   cudaGetSymbolAddress((void**)&cl, g_cl);

    const int TPB = 256;
    auto b4 = [](long long n) { return (unsigned)((n/4 + TPB - 1) / TPB); };

    // 1. Split inputs to bf16 hi/lo
    split_arr<<<b4((long long)NTOK*DMODEL), TPB>>>(x,  xh,  xl,  (long long)NTOK*DMODEL/4);
    split_arr<<<b4((long long)QO*DMODEL),   TPB>>>(wq, wqh, wql, (long long)QO*DMODEL/4);
    split_arr<<<b4((long long)KO*DMODEL),   TPB>>>(wk, wkh, wkl, (long long)KO*DMODEL/4);
    split_arr<<<b4((long long)KO*DMODEL),   TPB>>>(wv, wvh, wvl, (long long)KO*DMODEL/4);
    split_arr<<<b4((long long)DMODEL*QO),   TPB>>>(wo, woh, wol, (long long)DMODEL*QO/4);

    // 2. Projections (pipelined tensor-core GEMM)
    int g_sh = 2 * 4 * 128 * 40 * (int)sizeof(__nv_bfloat16);  // 81920
    cudaFuncSetAttribute(gemm_sp, cudaFuncAttributeMaxDynamicSharedMemorySize, g_sh);
    gemm_sp<<<dim3(QO/128, NTOK/128), TPB, g_sh>>>(xh, xl, wqh, wql, Qp, QO, DMODEL);
    gemm_sp<<<dim3(KO/128, NTOK/128), TPB, g_sh>>>(xh, xl, wkh, wkl, Kp, KO, DMODEL);
    gemm_sp<<<dim3(KO/128, NTOK/128), TPB, g_sh>>>(xh, xl, wvh, wvl, Vp, KO, DMODEL);

    // 3. RoPE + split; V transpose + split
    rope_split<<<(unsigned)(((long long)NTOK*QHEADS*64 + TPB-1)/TPB), TPB>>>(Qp, pos, Qhp, Qlp, QHEADS);
    rope_split<<<(unsigned)(((long long)NTOK*KVHEADS*64 + TPB-1)/TPB), TPB>>>(Kp, pos, Khp, Klp, KVHEADS);
    vtrans_split<<<(unsigned)(((long long)NTOK*KO + TPB-1)/TPB), TPB>>>(Vp, Vth, Vtl);

    // 4. Fused flash attention
    int fl_sh = (4 * 64 * 136 + 2 * 128 * 72) * (int)sizeof(__nv_bfloat16); // 106496
    cudaFuncSetAttribute(flash_tc, cudaFuncAttributeMaxDynamicSharedMemorySize, fl_sh);
    flash_tc<<<dim3(TSZ/64, QHEADS, BSZ), 128, fl_sh>>>(Qhp, Qlp, Khp, Klp, Vth, Vtl, Cp);

    // 5. Output projection
    split_arr<<<b4((long long)NTOK*QO), TPB>>>(Cp, ch, cl, (long long)NTOK*QO/4);
    gemm_sp<<<dim3(DMODEL/128, NTOK/128), TPB, g_sh>>>(ch, cl, woh, wol, out, DMODEL, QO);
}